// round 7
// baseline (speedup 1.0000x reference)
#include <cuda_runtime.h>
#include <math.h>
#include <stdint.h>

// ---------------------------------------------------------------------------
// UNetMidBlockCausal3D: resnet -> causal frame attention -> resnet
// B=1, C=512, T=8, H=32, W=32  => S = 8192 positions, 32 groups of 16 chans.
// Channels-last internally: A[s, c].  All big GEMMs: TF32 mma.sync.m16n8k8,
// cp.async 3-stage pipeline, k-permuted 64B smem rows so one LDS.128 yields
// both k8-group fragments conflict-free.
//   smem col' of logical k: ((k&7)>>1)*4 + (k>>3)*2 + (k&1)
//   float4 at [row][fc*4] = { k=2fc, 2fc+1, 8+2fc, 8+2fc+1 }  (g0: xy, g1: zw)
// mma k-positions (fc, fc+4) carry logical ks (2fc, 2fc+1) consistently for
// A and B (relabeling within a k8 group is sum-invariant).
// ---------------------------------------------------------------------------

#define S_TOT 8192
#define C_DIM 512
#define NG    32
#define GSZ   16

#define BM 128
#define BN 128
#define BK 16
#define STG_BYTES (BM * BK * 4)   // 8192 per tile per stage

// Scratch (device globals; runtime allocation is forbidden)
__device__ float g_X[S_TOT * C_DIM];          // 0: residual stream (fp32)
__device__ float g_N[S_TOT * C_DIM];          // 1: normalized (tf32-rounded)
__device__ float g_H[S_TOT * C_DIM];          // 2: conv intermediate / Vt
__device__ float g_Q[S_TOT * C_DIM];          // 3 (tf32)
__device__ float g_K[S_TOT * C_DIM];          // 4 (tf32)
__device__ float g_V[S_TOT * C_DIM];          // 5 (tf32)
__device__ float g_O[S_TOT * C_DIM];          // 6 (tf32)
__device__ float g_S[(size_t)S_TOT * S_TOT];  // 7: scores / exp (256 MB)
__device__ float g_Wc[27 * C_DIM * C_DIM];    // 8: conv W [tap][co][ci] (tf32)
__device__ float g_Wl[C_DIM * C_DIM];         // 9: linear W [o][c] (tf32)
__device__ float g_mu[NG];
__device__ float g_rs[NG];
__device__ float g_inv[S_TOT];                // per-row 1/sum(exp)

__device__ __forceinline__ float* BUF(int id) {
    switch (id) {
        case 0: return g_X;  case 1: return g_N;  case 2: return g_H;
        case 3: return g_Q;  case 4: return g_K;  case 5: return g_V;
        case 6: return g_O;  case 7: return g_S;  case 8: return g_Wc;
        default: return g_Wl;
    }
}

__device__ __forceinline__ float tf32r(float x) {
    uint32_t o;
    asm("cvt.rna.tf32.f32 %0, %1;" : "=r"(o) : "f"(x));
    return __uint_as_float(o);
}

// D += A(16x8) * B(8x8), tf32 row.col.
__device__ __forceinline__ void mma8(float* c, float2 alo, float2 ahi, float2 b) {
    asm volatile(
        "mma.sync.aligned.m16n8k8.row.col.f32.tf32.tf32.f32 "
        "{%0,%1,%2,%3}, {%4,%5,%6,%7}, {%8,%9}, {%0,%1,%2,%3};\n"
        : "+f"(c[0]), "+f"(c[1]), "+f"(c[2]), "+f"(c[3])
        : "r"(__float_as_uint(alo.x)), "r"(__float_as_uint(ahi.x)),
          "r"(__float_as_uint(alo.y)), "r"(__float_as_uint(ahi.y)),
          "r"(__float_as_uint(b.x)),   "r"(__float_as_uint(b.y)));
}

__device__ __forceinline__ void cpa8(uint32_t dst, const void* src) {
    asm volatile("cp.async.ca.shared.global [%0], [%1], 8;\n"
                 :: "r"(dst), "l"(src));
}
#define CP_COMMIT() asm volatile("cp.async.commit_group;\n" ::: "memory")
#define CP_WAIT1()  asm volatile("cp.async.wait_group 1;\n" ::: "memory")

// ---------------------------------------------------------------------------
// 32x32-tiled transpose: dst[c][r] = src[r][c].  src is rows x cols.
// ---------------------------------------------------------------------------
__global__ void transpose_k(const float* src_ext, int src_id,
                            float* dst_ext, int dst_id,
                            int rows, int cols) {
    const float* src = src_ext ? src_ext : BUF(src_id);
    float* dst = dst_ext ? dst_ext : BUF(dst_id);
    __shared__ float tile[32][33];
    int c0 = blockIdx.x * 32, r0 = blockIdx.y * 32;
    int c = c0 + threadIdx.x;
    #pragma unroll
    for (int j = threadIdx.y; j < 32; j += 8)
        tile[j][threadIdx.x] = src[(size_t)(r0 + j) * cols + c];
    __syncthreads();
    int r2 = r0 + threadIdx.x;
    #pragma unroll
    for (int j = threadIdx.y; j < 32; j += 8)
        dst[(size_t)(c0 + j) * rows + r2] = tile[threadIdx.x][j];
}

// Conv weight prep: g_Wc[tap][co][ci] = tf32(w[co][ci][tap])
__global__ void wconv_tr(const float* __restrict__ w) {
    int idx = blockIdx.x * 256 + threadIdx.x;
    int tap = idx >> 18;
    int rem = idx & 262143;
    int co  = rem >> 9;
    int ci  = rem & 511;
    g_Wc[idx] = tf32r(w[(size_t)co * (C_DIM * 27) + ci * 27 + tap]);
}

// Linear weight prep: g_Wl = tf32(w), layout already [o][c] = [n][k]
__global__ void round_copy(const float* __restrict__ w) {
    int idx = blockIdx.x * 256 + threadIdx.x;
    g_Wl[idx] = tf32r(w[idx]);
}

// ---------------------------------------------------------------------------
// GroupNorm stats.  gn_stats: channels-last A[s,c] scratch buffer.
// gn_stats_raw: NCDHW external input (group = 16 contiguous channel planes).
// ---------------------------------------------------------------------------
__global__ void gn_stats(int aid) {
    const float* A = BUF(aid);
    __shared__ float sh[1024], sh2[1024];
    int g = blockIdx.x, tid = threadIdx.x;
    const float* base = A + g * GSZ;
    float s = 0.f, ss = 0.f;
    for (int idx = tid; idx < S_TOT * GSZ; idx += 1024) {
        int r = idx >> 4, c = idx & 15;
        float v = base[(size_t)r * C_DIM + c];
        s += v; ss += v * v;
    }
    sh[tid] = s; sh2[tid] = ss;
    __syncthreads();
    for (int o = 512; o > 0; o >>= 1) {
        if (tid < o) { sh[tid] += sh[tid + o]; sh2[tid] += sh2[tid + o]; }
        __syncthreads();
    }
    if (tid == 0) {
        const float invn = 1.f / (float)(S_TOT * GSZ);
        float m   = sh[0] * invn;
        float var = sh2[0] * invn - m * m;
        g_mu[g] = m;
        g_rs[g] = rsqrtf(var + 1e-6f);
    }
}

__global__ void gn_stats_raw(const float* __restrict__ in) {
    __shared__ float sh[1024], sh2[1024];
    int g = blockIdx.x, tid = threadIdx.x;
    const float* base = in + (size_t)g * GSZ * S_TOT;   // 16 contiguous planes
    float s = 0.f, ss = 0.f;
    for (int idx = tid; idx < S_TOT * GSZ; idx += 1024) {
        float v = base[idx];
        s += v; ss += v * v;
    }
    sh[tid] = s; sh2[tid] = ss;
    __syncthreads();
    for (int o = 512; o > 0; o >>= 1) {
        if (tid < o) { sh[tid] += sh[tid + o]; sh2[tid] += sh2[tid + o]; }
        __syncthreads();
    }
    if (tid == 0) {
        const float invn = 1.f / (float)(S_TOT * GSZ);
        float m   = sh[0] * invn;
        float var = sh2[0] * invn - m * m;
        g_mu[g] = m;
        g_rs[g] = rsqrtf(var + 1e-6f);
    }
}

// GroupNorm apply (+ optional SiLU); channels-last in/out, writes g_N.
__global__ void gn_apply(int aid, const float* __restrict__ sc,
                         const float* __restrict__ bi, int do_silu) {
    const float* A = BUF(aid);
    int idx = blockIdx.x * 256 + threadIdx.x;
    float v = A[idx];
    int c = idx & 511;
    int g = c >> 4;
    float y = (v - g_mu[g]) * g_rs[g] * sc[c] + bi[c];
    if (do_silu) y = y * (1.f / (1.f + __expf(-y)));
    g_N[idx] = tf32r(y);
}

// Fused: NCDHW input -> GN + SiLU -> transpose -> g_N[s][c] (tf32-rounded).
__global__ void gn_tr_apply(const float* __restrict__ in,
                            const float* __restrict__ sc,
                            const float* __restrict__ bi) {
    __shared__ float tile[32][33];
    int s0 = blockIdx.x * 32, c0 = blockIdx.y * 32;
    int s = s0 + threadIdx.x;
    #pragma unroll
    for (int j = threadIdx.y; j < 32; j += 8) {
        int ch = c0 + j;
        int g = ch >> 4;
        float v = in[(size_t)ch * S_TOT + s];
        float y = (v - g_mu[g]) * g_rs[g] * sc[ch] + bi[ch];
        y = y * (1.f / (1.f + __expf(-y)));
        tile[j][threadIdx.x] = tf32r(y);
    }
    __syncthreads();
    int s2 = s0 + threadIdx.y;
    #pragma unroll
    for (int j = threadIdx.y; j < 32; j += 8)
        g_N[(size_t)(s0 + j) * C_DIM + c0 + threadIdx.x] = tile[threadIdx.x][j];
    (void)s2;
}

// ---------------------------------------------------------------------------
// TF32 tensor-core GEMM: C[m,n] = sum_k A[m,k]*B[n,k]  (B is [n][k] row-major)
//   MODE 0: linear (K=512).
//   MODE 1: conv (K=27*512): A rows gathered via inline tap/clamp arithmetic;
//           B = g_Wc [tap][n][kloc].
//   MODE 2: scores: causal tile skip; epilogue *scale; C = g_S (ldc 8192).
//   MODE 3: PV: K limited to causal prefix; epilogue *g_inv[row].
// 128x128x16 tile, 8 warps (4m x 2n), warp tile 32x64, cp.async 3-stage,
// one __syncthreads per stage.
// ---------------------------------------------------------------------------
template <int MODE>
__global__ __launch_bounds__(256, 2)
void mma_gemm(int aid, int bid, const float* __restrict__ bias,
              int rid, int cid, int Ktot, int lda, int ldb, int ldc,
              float scale, int do_round) {
    const float* A  = BUF(aid);
    const float* Bm = BUF(bid);
    const float* resid = (rid >= 0) ? BUF(rid) : nullptr;
    float* C = BUF(cid);

    const int m0 = blockIdx.y * BM;
    const int n0 = blockIdx.x * BN;
    if (MODE == 2 && n0 >= (((m0 >> 10) + 1) << 10)) return;

    __shared__ __align__(16) float As[3][BM][BK];   // 3 x 8KB
    __shared__ __align__(16) float Bs[3][BN][BK];   // 3 x 8KB  (48KB total)

    const int tid  = threadIdx.x;
    const int lane = tid & 31;
    const int warp = tid >> 5;
    const int wm = warp >> 1;   // m offset wm*32
    const int wn = warp & 1;    // n offset wn*64
    const int fr = lane >> 2;   // 0..7
    const int fc = lane & 3;    // 0..3

    int Keff = Ktot;
    if (MODE == 3) Keff = ((m0 >> 10) + 1) << 10;
    const int nkt = Keff / BK;

    // ---- per-thread fetch precomputation ----
    // thread covers logical ks [c4*4, c4*4+4) of its row; two 8B chunks land
    // at permuted cols C0 and C0+4.
    const float* aptr[2];
    const float* bptr[2];
    int tv[2], hv[2], wv[2], koff[2];
    uint32_t sA[2], sB[2];
    #pragma unroll
    for (int it = 0; it < 2; it++) {
        int f4 = tid + it * 256;
        int row = f4 >> 2, c4 = f4 & 3;
        koff[it] = c4 * 4;
        int C0 = ((c4 & 1) << 3) | ((c4 >> 1) << 1);
        if (MODE == 1) {
            int s = m0 + row;
            tv[it] = s >> 10; hv[it] = (s >> 5) & 31; wv[it] = s & 31;
            bptr[it] = Bm + (size_t)(n0 + row) * C_DIM + koff[it];
        } else {
            aptr[it] = A + (size_t)(m0 + row) * lda + koff[it];
            bptr[it] = Bm + (size_t)(n0 + row) * ldb + koff[it];
        }
        sA[it] = (uint32_t)__cvta_generic_to_shared(&As[0][row][C0]);
        sB[it] = (uint32_t)__cvta_generic_to_shared(&Bs[0][row][C0]);
    }

    auto fetch = [&](int kt, int slot) {
        const int kk = kt * BK;
        const uint32_t off = (uint32_t)slot * STG_BYTES;
        if (MODE == 1) {
            const int tap  = kk >> 9;
            const int kloc = kk & 511;
            const int kd = tap / 9;
            const int r9 = tap - kd * 9;
            const int kh = r9 / 3;
            const int kw = r9 - kh * 3;
            #pragma unroll
            for (int it = 0; it < 2; it++) {
                int tt = tv[it] + kd - 2; if (tt < 0) tt = 0;
                int hh = hv[it] + kh - 1; hh = hh < 0 ? 0 : (hh > 31 ? 31 : hh);
                int ww = wv[it] + kw - 1; ww = ww < 0 ? 0 : (ww > 31 ? 31 : ww);
                const float* sa = A + (size_t)((tt << 10) | (hh << 5) | ww) * C_DIM
                                    + kloc + koff[it];
                const float* sb = bptr[it] + (size_t)tap * (C_DIM * C_DIM) + kloc;
                cpa8(sA[it] + off,      sa);
                cpa8(sA[it] + off + 16, sa + 2);
                cpa8(sB[it] + off,      sb);
                cpa8(sB[it] + off + 16, sb + 2);
            }
        } else {
            #pragma unroll
            for (int it = 0; it < 2; it++) {
                cpa8(sA[it] + off,      aptr[it] + kk);
                cpa8(sA[it] + off + 16, aptr[it] + kk + 2);
                cpa8(sB[it] + off,      bptr[it] + kk);
                cpa8(sB[it] + off + 16, bptr[it] + kk + 2);
            }
        }
    };

    float acc[2][8][4];
    #pragma unroll
    for (int mi = 0; mi < 2; mi++)
        #pragma unroll
        for (int ni = 0; ni < 8; ni++)
            #pragma unroll
            for (int r = 0; r < 4; r++) acc[mi][ni][r] = 0.f;

    auto compute = [&](int s) {
        float4 av[2][2];
        #pragma unroll
        for (int mi = 0; mi < 2; mi++) {
            av[mi][0] = *(const float4*)&As[s][wm * 32 + mi * 16 + fr][fc * 4];
            av[mi][1] = *(const float4*)&As[s][wm * 32 + mi * 16 + fr + 8][fc * 4];
        }
        #pragma unroll
        for (int nh = 0; nh < 2; nh++) {
            float4 bv[4];
            #pragma unroll
            for (int nj = 0; nj < 4; nj++)
                bv[nj] = *(const float4*)&Bs[s][wn * 64 + (nh * 4 + nj) * 8 + fr][fc * 4];
            #pragma unroll
            for (int mi = 0; mi < 2; mi++)
                #pragma unroll
                for (int nj = 0; nj < 4; nj++) {
                    mma8(acc[mi][nh * 4 + nj],
                         make_float2(av[mi][0].x, av[mi][0].y),
                         make_float2(av[mi][1].x, av[mi][1].y),
                         make_float2(bv[nj].x, bv[nj].y));
                    mma8(acc[mi][nh * 4 + nj],
                         make_float2(av[mi][0].z, av[mi][0].w),
                         make_float2(av[mi][1].z, av[mi][1].w),
                         make_float2(bv[nj].z, bv[nj].w));
                }
        }
    };

    // ---- prologue: 2 stages in flight ----
    fetch(0, 0); CP_COMMIT();
    fetch(1, 1); CP_COMMIT();

    int slot = 0;
    for (int kt = 0; kt < nkt; kt++) {
        CP_WAIT1();            // stage kt landed (<=1 group pending)
        __syncthreads();       // visible to all; prior stage fully consumed
        if (kt + 2 < nkt) fetch(kt + 2, (slot + 2) % 3);
        CP_COMMIT();           // keep group count in lockstep
        compute(slot);
        slot = (slot + 1) % 3;
    }

    // Epilogue: c0,c1 -> row fr, cols 2fc,2fc+1; c2,c3 -> row fr+8.
    #pragma unroll
    for (int mi = 0; mi < 2; mi++) {
        #pragma unroll
        for (int h = 0; h < 2; h++) {
            int row = m0 + wm * 32 + mi * 16 + h * 8 + fr;
            float rsc = (MODE == 3) ? g_inv[row] : scale;
            #pragma unroll
            for (int ni = 0; ni < 8; ni++) {
                int col = n0 + wn * 64 + ni * 8 + 2 * fc;
                float v0 = acc[mi][ni][h * 2 + 0] * rsc;
                float v1 = acc[mi][ni][h * 2 + 1] * rsc;
                if (bias) { v0 += bias[col]; v1 += bias[col + 1]; }
                if (resid) {
                    float2 r = *(const float2*)(resid + (size_t)row * ldc + col);
                    v0 += r.x; v1 += r.y;
                }
                if (do_round) { v0 = tf32r(v0); v1 = tf32r(v1); }
                float2 o; o.x = v0; o.y = v1;
                *(float2*)(C + (size_t)row * ldc + col) = o;
            }
        }
    }
}

// ---------------------------------------------------------------------------
// Softmax over causal prefix L = (frame+1)*1024.  Stores tf32-rounded,
// UNNORMALIZED exp in g_S; 1/sum in g_inv (PV epilogue applies it).
// ---------------------------------------------------------------------------
__global__ void softmax_rows() {
    const int q = blockIdx.x;
    const int L = ((q >> 10) + 1) << 10;
    float* row = g_S + (size_t)q * S_TOT;
    __shared__ float red[256];
    const int tid = threadIdx.x;

    float m = -1e30f;
    for (int i = tid; i < L; i += 256) m = fmaxf(m, row[i]);
    red[tid] = m; __syncthreads();
    for (int o = 128; o > 0; o >>= 1) {
        if (tid < o) red[tid] = fmaxf(red[tid], red[tid + o]);
        __syncthreads();
    }
    m = red[0];
    __syncthreads();

    float s = 0.f;
    for (int i = tid; i < L; i += 256) {
        float e = tf32r(__expf(row[i] - m));
        row[i] = e;
        s += e;
    }
    red[tid] = s; __syncthreads();
    for (int o = 128; o > 0; o >>= 1) {
        if (tid < o) red[tid] += red[tid + o];
        __syncthreads();
    }
    if (tid == 0) g_inv[q] = 1.f / red[0];
}

// ---------------------------------------------------------------------------
// Host orchestration — kernel launches only (graph-capture safe).
// Launch order puts the first conv GEMM at index 3 (ncu capture slot).
// ---------------------------------------------------------------------------
extern "C" void kernel_launch(void* const* d_in, const int* in_sizes, int n_in,
                              void* d_out, int out_size) {
    (void)in_sizes; (void)n_in; (void)out_size;

    const float* in = (const float*)d_in[0];
    float* out = (float*)d_out;

    const dim3 gemm_grid(C_DIM / BN, S_TOT / BM);   // (4, 64)
    const int EW_BLOCKS = S_TOT * C_DIM / 256;      // 16384
    const int WC_BLOCKS = 27 * C_DIM * C_DIM / 256; // 27648
    const int WL_BLOCKS = C_DIM * C_DIM / 256;      // 1024
    const dim3 tb(32, 8);

    // ---- resnet block 0, first conv: fused front-end (gemm at launch #3) ----
    {
        const float* n1s = (const float*)d_in[1];
        const float* n1b = (const float*)d_in[2];
        const float* w1  = (const float*)d_in[3];
        const float* b1  = (const float*)d_in[4];

        wconv_tr<<<WC_BLOCKS, 256>>>(w1);                       // 0
        gn_stats_raw<<<NG, 1024>>>(in);                         // 1
        gn_tr_apply<<<dim3(S_TOT / 32, C_DIM / 32), tb>>>(in, n1s, n1b);  // 2
        mma_gemm<1><<<gemm_grid, 256>>>(1, 8, b1, -1, 2,        // 3 <- profiled
                                        27 * C_DIM, C_DIM, C_DIM, C_DIM, 1.f, 0);
        // residual stream X = transpose(in), needed by conv2 epilogue
        transpose_k<<<dim3(S_TOT / 32, C_DIM / 32), tb>>>(in, -1, nullptr, 0,
                                                          C_DIM, S_TOT);  // 4
        const float* n2s = (const float*)d_in[5];
        const float* n2b = (const float*)d_in[6];
        const float* w2  = (const float*)d_in[7];
        const float* b2  = (const float*)d_in[8];
        gn_stats<<<NG, 1024>>>(2);
        gn_apply<<<EW_BLOCKS, 256>>>(2, n2s, n2b, 1);
        wconv_tr<<<WC_BLOCKS, 256>>>(w2);
        mma_gemm<1><<<gemm_grid, 256>>>(1, 8, b2, 0, 0,
                                        27 * C_DIM, C_DIM, C_DIM, C_DIM, 1.f, 0);
    }

    auto resnet = [&](int base) {
        const float* n1s = (const float*)d_in[base + 0];
        const float* n1b = (const float*)d_in[base + 1];
        const float* w1  = (const float*)d_in[base + 2];
        const float* b1  = (const float*)d_in[base + 3];
        const float* n2s = (const float*)d_in[base + 4];
        const float* n2b = (const float*)d_in[base + 5];
        const float* w2  = (const float*)d_in[base + 6];
        const float* b2  = (const float*)d_in[base + 7];

        gn_stats<<<NG, 1024>>>(0);
        gn_apply<<<EW_BLOCKS, 256>>>(0, n1s, n1b, 1);
        wconv_tr<<<WC_BLOCKS, 256>>>(w1);
        mma_gemm<1><<<gemm_grid, 256>>>(1, 8, b1, -1, 2,
                                        27 * C_DIM, C_DIM, C_DIM, C_DIM, 1.f, 0);
        gn_stats<<<NG, 1024>>>(2);
        gn_apply<<<EW_BLOCKS, 256>>>(2, n2s, n2b, 1);
        wconv_tr<<<WC_BLOCKS, 256>>>(w2);
        mma_gemm<1><<<gemm_grid, 256>>>(1, 8, b2, 0, 0,
                                        27 * C_DIM, C_DIM, C_DIM, C_DIM, 1.f, 0);
    };

    // ---- causal frame attention (inputs 17..26) ----
    {
        const float* gns = (const float*)d_in[17];
        const float* gnb = (const float*)d_in[18];
        const float* wq  = (const float*)d_in[19];
        const float* bq  = (const float*)d_in[20];
        const float* wk  = (const float*)d_in[21];
        const float* bk  = (const float*)d_in[22];
        const float* wv  = (const float*)d_in[23];
        const float* bv  = (const float*)d_in[24];
        const float* wo  = (const float*)d_in[25];
        const float* bo  = (const float*)d_in[26];

        gn_stats<<<NG, 1024>>>(0);
        gn_apply<<<EW_BLOCKS, 256>>>(0, gns, gnb, 0);

        round_copy<<<WL_BLOCKS, 256>>>(wq);
        mma_gemm<0><<<gemm_grid, 256>>>(1, 9, bq, -1, 3,
                                        C_DIM, C_DIM, C_DIM, C_DIM, 1.f, 1);
        round_copy<<<WL_BLOCKS, 256>>>(wk);
        mma_gemm<0><<<gemm_grid, 256>>>(1, 9, bk, -1, 4,
                                        C_DIM, C_DIM, C_DIM, C_DIM, 1.f, 1);
        round_copy<<<WL_BLOCKS, 256>>>(wv);
        mma_gemm<0><<<gemm_grid, 256>>>(1, 9, bv, -1, 5,
                                        C_DIM, C_DIM, C_DIM, C_DIM, 1.f, 1);

        // scores: S[q,k] = scale * Q.K^T  (block-causal skip)
        const float scale = 0.044194173824159216f;  // 512^-0.5
        mma_gemm<2><<<dim3(S_TOT / BN, S_TOT / BM), 256>>>(
            3, 4, nullptr, -1, 7, C_DIM, C_DIM, C_DIM, S_TOT, scale, 0);
        softmax_rows<<<S_TOT, 256>>>();

        // Vt = V^T into g_H (tf32 values preserved)
        transpose_k<<<dim3(C_DIM / 32, S_TOT / 32), tb>>>(nullptr, 5, nullptr, 2,
                                                          S_TOT, C_DIM);
        // O = P @ V  (A = exp scores, B = Vt [c][s]); epilogue * g_inv, round
        mma_gemm<3><<<gemm_grid, 256>>>(7, 2, nullptr, -1, 6,
                                        S_TOT, S_TOT, S_TOT, C_DIM, 1.f, 1);

        round_copy<<<WL_BLOCKS, 256>>>(wo);
        mma_gemm<0><<<gemm_grid, 256>>>(6, 9, bo, 0, 0,
                                        C_DIM, C_DIM, C_DIM, C_DIM, 1.f, 0);
    }

    // ---- resnet block 1 (inputs 9..16) ----
    resnet(9);

    // channels-last g_X[8192][512] -> NCDHW out [512][8192]
    transpose_k<<<dim3(C_DIM / 32, S_TOT / 32), tb>>>(nullptr, 0, out, -1, S_TOT, C_DIM);
}

// round 10
// speedup vs baseline: 1.1472x; 1.1472x over previous
#include <cuda_runtime.h>
#include <math.h>
#include <stdint.h>

// ---------------------------------------------------------------------------
// UNetMidBlockCausal3D: resnet -> causal frame attention -> resnet
// B=1, C=512, T=8, H=32, W=32 => S = 8192 positions, 32 groups of 16 chans.
// Channels-last internally: A[s, c].  All GEMMs: TF32 mma.sync.m16n8k8 with
// fp32 accumulate, cp.async 16B 2-stage pipeline, plain [row][16] smem tiles.
// k-partition trick: BK=16 splits into two mma k8-groups as ANY partition;
// position (fc, fc+4) of group g carries logical ks (4fc+2g, 4fc+2g+1), so a
// single LDS.128 at [row][fc*4] feeds both groups (x,y=g0; z,w=g1),
// conflict-free (row stride 16 words => 8-lane phase covers 32 banks).
// ---------------------------------------------------------------------------

#define S_TOT 8192
#define C_DIM 512
#define NG    32
#define GSZ   16

#define BM 128
#define BN 128
#define BK 16
#define STG_BYTES (BM * BK * 4)   // 8192 per tile per stage

// Scratch (device globals; runtime allocation is forbidden)
__device__ float g_X[S_TOT * C_DIM];          // 0: residual stream (fp32)
__device__ float g_N[S_TOT * C_DIM];          // 1: normalized (tf32-rounded)
__device__ float g_H[S_TOT * C_DIM];          // 2: conv intermediate / Vt
__device__ float g_Q[S_TOT * C_DIM];          // 3 (tf32)
__device__ float g_K[S_TOT * C_DIM];          // 4 (tf32)
__device__ float g_V[S_TOT * C_DIM];          // 5 (tf32)
__device__ float g_O[S_TOT * C_DIM];          // 6 (tf32)
__device__ float g_S[(size_t)S_TOT * S_TOT];  // 7: scores / exp (256 MB)
__device__ float g_Wc[27 * C_DIM * C_DIM];    // 8: conv W [tap][co][ci] (tf32)
__device__ float g_Wl[C_DIM * C_DIM];         // 9: linear W [o][c] (tf32)
__device__ float g_mu[NG];
__device__ float g_rs[NG];
__device__ float g_inv[S_TOT];                // per-row 1/sum(exp)

__device__ __forceinline__ float* BUF(int id) {
    switch (id) {
        case 0: return g_X;  case 1: return g_N;  case 2: return g_H;
        case 3: return g_Q;  case 4: return g_K;  case 5: return g_V;
        case 6: return g_O;  case 7: return g_S;  case 8: return g_Wc;
        default: return g_Wl;
    }
}

__device__ __forceinline__ float tf32r(float x) {
    uint32_t o;
    asm("cvt.rna.tf32.f32 %0, %1;" : "=r"(o) : "f"(x));
    return __uint_as_float(o);
}

// D += A(16x8) * B(8x8), tf32 row.col.  alo={a0,a2} (row fr), ahi={a1,a3}.
__device__ __forceinline__ void mma8(float* c, float2 alo, float2 ahi, float2 b) {
    asm volatile(
        "mma.sync.aligned.m16n8k8.row.col.f32.tf32.tf32.f32 "
        "{%0,%1,%2,%3}, {%4,%5,%6,%7}, {%8,%9}, {%0,%1,%2,%3};\n"
        : "+f"(c[0]), "+f"(c[1]), "+f"(c[2]), "+f"(c[3])
        : "r"(__float_as_uint(alo.x)), "r"(__float_as_uint(ahi.x)),
          "r"(__float_as_uint(alo.y)), "r"(__float_as_uint(ahi.y)),
          "r"(__float_as_uint(b.x)),   "r"(__float_as_uint(b.y)));
}

__device__ __forceinline__ void cpa16(uint32_t dst, const void* src) {
    asm volatile("cp.async.cg.shared.global [%0], [%1], 16;\n" :: "r"(dst), "l"(src));
}
#define CP_COMMIT() asm volatile("cp.async.commit_group;\n" ::: "memory")
#define CP_WAIT1()  asm volatile("cp.async.wait_group 1;\n" ::: "memory")

// ---------------------------------------------------------------------------
// 32x32-tiled transpose: dst[c][r] = src[r][c].  src is rows x cols.
// ---------------------------------------------------------------------------
__global__ void transpose_k(const float* src_ext, int src_id,
                            float* dst_ext, int dst_id,
                            int rows, int cols) {
    const float* src = src_ext ? src_ext : BUF(src_id);
    float* dst = dst_ext ? dst_ext : BUF(dst_id);
    __shared__ float tile[32][33];
    int c0 = blockIdx.x * 32, r0 = blockIdx.y * 32;
    int c = c0 + threadIdx.x;
    #pragma unroll
    for (int j = threadIdx.y; j < 32; j += 8)
        tile[j][threadIdx.x] = src[(size_t)(r0 + j) * cols + c];
    __syncthreads();
    int r2 = r0 + threadIdx.x;
    #pragma unroll
    for (int j = threadIdx.y; j < 32; j += 8)
        dst[(size_t)(c0 + j) * rows + r2] = tile[threadIdx.x][j];
}

// Conv weight prep: g_Wc[tap][co][ci] = tf32(w[co][ci][tap])
__global__ void wconv_tr(const float* __restrict__ w) {
    int idx = blockIdx.x * 256 + threadIdx.x;
    int tap = idx >> 18;
    int rem = idx & 262143;
    int co  = rem >> 9;
    int ci  = rem & 511;
    g_Wc[idx] = tf32r(w[(size_t)co * (C_DIM * 27) + ci * 27 + tap]);
}

__global__ void round_copy(const float* __restrict__ w) {
    int idx = blockIdx.x * 256 + threadIdx.x;
    g_Wl[idx] = tf32r(w[idx]);
}

// ---------------------------------------------------------------------------
// GroupNorm stats / apply
// ---------------------------------------------------------------------------
__global__ void gn_stats(int aid) {
    const float* A = BUF(aid);
    __shared__ float sh[1024], sh2[1024];
    int g = blockIdx.x, tid = threadIdx.x;
    const float* base = A + g * GSZ;
    float s = 0.f, ss = 0.f;
    for (int idx = tid; idx < S_TOT * GSZ; idx += 1024) {
        int r = idx >> 4, c = idx & 15;
        float v = base[(size_t)r * C_DIM + c];
        s += v; ss += v * v;
    }
    sh[tid] = s; sh2[tid] = ss;
    __syncthreads();
    for (int o = 512; o > 0; o >>= 1) {
        if (tid < o) { sh[tid] += sh[tid + o]; sh2[tid] += sh2[tid + o]; }
        __syncthreads();
    }
    if (tid == 0) {
        const float invn = 1.f / (float)(S_TOT * GSZ);
        float m   = sh[0] * invn;
        float var = sh2[0] * invn - m * m;
        g_mu[g] = m;
        g_rs[g] = rsqrtf(var + 1e-6f);
    }
}

__global__ void gn_stats_raw(const float* __restrict__ in) {
    __shared__ float sh[1024], sh2[1024];
    int g = blockIdx.x, tid = threadIdx.x;
    const float* base = in + (size_t)g * GSZ * S_TOT;
    float s = 0.f, ss = 0.f;
    for (int idx = tid; idx < S_TOT * GSZ; idx += 1024) {
        float v = base[idx];
        s += v; ss += v * v;
    }
    sh[tid] = s; sh2[tid] = ss;
    __syncthreads();
    for (int o = 512; o > 0; o >>= 1) {
        if (tid < o) { sh[tid] += sh[tid + o]; sh2[tid] += sh2[tid + o]; }
        __syncthreads();
    }
    if (tid == 0) {
        const float invn = 1.f / (float)(S_TOT * GSZ);
        float m   = sh[0] * invn;
        float var = sh2[0] * invn - m * m;
        g_mu[g] = m;
        g_rs[g] = rsqrtf(var + 1e-6f);
    }
}

__global__ void gn_apply(int aid, const float* __restrict__ sc,
                         const float* __restrict__ bi, int do_silu) {
    const float* A = BUF(aid);
    int idx = blockIdx.x * 256 + threadIdx.x;
    float v = A[idx];
    int c = idx & 511;
    int g = c >> 4;
    float y = (v - g_mu[g]) * g_rs[g] * sc[c] + bi[c];
    if (do_silu) y = y * (1.f / (1.f + __expf(-y)));
    g_N[idx] = tf32r(y);
}

// Fused: NCDHW input -> GN + SiLU -> transpose -> g_N[s][c] (tf32-rounded).
__global__ void gn_tr_apply(const float* __restrict__ in,
                            const float* __restrict__ sc,
                            const float* __restrict__ bi) {
    __shared__ float tile[32][33];
    int s0 = blockIdx.x * 32, c0 = blockIdx.y * 32;
    int s = s0 + threadIdx.x;
    #pragma unroll
    for (int j = threadIdx.y; j < 32; j += 8) {
        int ch = c0 + j;
        int g = ch >> 4;
        float v = in[(size_t)ch * S_TOT + s];
        float y = (v - g_mu[g]) * g_rs[g] * sc[ch] + bi[ch];
        y = y * (1.f / (1.f + __expf(-y)));
        tile[j][threadIdx.x] = tf32r(y);
    }
    __syncthreads();
    #pragma unroll
    for (int j = threadIdx.y; j < 32; j += 8)
        g_N[(size_t)(s0 + j) * C_DIM + c0 + threadIdx.x] = tile[threadIdx.x][j];
}

// ---------------------------------------------------------------------------
// TF32 tensor-core GEMM: C[m,n] = sum_k A[m,k]*B[n,k]  (B is [n][k] row-major)
//   MODE 0: linear (K=512).
//   MODE 1: conv (K=27*512): A rows gathered via inline tap/clamp arithmetic;
//           B = g_Wc [tap][n][kloc].
//   MODE 2: scores: causal tile skip; epilogue *scale; C = g_S (ldc 8192).
//   MODE 3: PV: K limited to causal prefix; epilogue *g_inv[row].
// 128x128x16 tile, 8 warps (4m x 2n), warp tile 32x64, cp.async 16B 2-stage,
// unpadded [row][16] tiles, one LDS.128 per fragment-row (both k8 groups).
// ---------------------------------------------------------------------------
template <int MODE>
__global__ __launch_bounds__(256, 2)
void mma_gemm(int aid, int bid, const float* __restrict__ bias,
              int rid, int cid, int Ktot, int lda, int ldb, int ldc,
              float scale, int do_round) {
    const float* A  = BUF(aid);
    const float* Bm = BUF(bid);
    const float* resid = (rid >= 0) ? BUF(rid) : nullptr;
    float* C = BUF(cid);

    const int m0 = blockIdx.y * BM;
    const int n0 = blockIdx.x * BN;
    if (MODE == 2 && n0 >= (((m0 >> 10) + 1) << 10)) return;

    __shared__ __align__(16) float As[2][BM][BK];   // 2 x 8KB
    __shared__ __align__(16) float Bs[2][BN][BK];   // 2 x 8KB  (32KB total)

    const int tid  = threadIdx.x;
    const int lane = tid & 31;
    const int warp = tid >> 5;
    const int wm = warp >> 1;   // m offset wm*32
    const int wn = warp & 1;    // n offset wn*64
    const int fr = lane >> 2;   // 0..7
    const int fc = lane & 3;    // 0..3

    int Keff = Ktot;
    if (MODE == 3) Keff = ((m0 >> 10) + 1) << 10;
    const int nkt = Keff / BK;

    // ---- per-thread fetch precomputation (2 x 16B per operand per stage) ----
    const float* aptr[2];
    const float* bptr[2];
    int tv[2], hv[2], wv[2], koff[2];
    uint32_t sA[2], sB[2];
    #pragma unroll
    for (int it = 0; it < 2; it++) {
        int f4 = tid + it * 256;
        int row = f4 >> 2, c4 = f4 & 3;
        koff[it] = c4 * 4;
        if (MODE == 1) {
            int s = m0 + row;
            tv[it] = s >> 10; hv[it] = (s >> 5) & 31; wv[it] = s & 31;
            bptr[it] = Bm + (size_t)(n0 + row) * C_DIM + koff[it];
        } else {
            aptr[it] = A + (size_t)(m0 + row) * lda + koff[it];
            bptr[it] = Bm + (size_t)(n0 + row) * ldb + koff[it];
        }
        sA[it] = (uint32_t)__cvta_generic_to_shared(&As[0][row][koff[it]]);
        sB[it] = (uint32_t)__cvta_generic_to_shared(&Bs[0][row][koff[it]]);
    }

    auto fetch = [&](int kt, int b) {
        const int kk = kt * BK;
        const uint32_t off = (uint32_t)b * STG_BYTES;
        if (MODE == 1) {
            const int tap  = kk >> 9;
            const int kloc = kk & 511;
            const int kd = tap / 9;
            const int r9 = tap - kd * 9;
            const int kh = r9 / 3;
            const int kw = r9 - kh * 3;
            #pragma unroll
            for (int it = 0; it < 2; it++) {
                int tt = tv[it] + kd - 2; if (tt < 0) tt = 0;
                int hh = hv[it] + kh - 1; hh = hh < 0 ? 0 : (hh > 31 ? 31 : hh);
                int ww = wv[it] + kw - 1; ww = ww < 0 ? 0 : (ww > 31 ? 31 : ww);
                int arow = (tt << 10) | (hh << 5) | ww;
                cpa16(sA[it] + off, A + (size_t)arow * C_DIM + kloc + koff[it]);
                cpa16(sB[it] + off, bptr[it] + (size_t)tap * (C_DIM * C_DIM) + kloc);
            }
        } else {
            #pragma unroll
            for (int it = 0; it < 2; it++) {
                cpa16(sA[it] + off, aptr[it] + kk);
                cpa16(sB[it] + off, bptr[it] + kk);
            }
        }
    };

    float acc[2][8][4];
    #pragma unroll
    for (int mi = 0; mi < 2; mi++)
        #pragma unroll
        for (int ni = 0; ni < 8; ni++)
            #pragma unroll
            for (int r = 0; r < 4; r++) acc[mi][ni][r] = 0.f;

    auto compute = [&](int s) {
        float4 av[2][2];
        #pragma unroll
        for (int mi = 0; mi < 2; mi++) {
            av[mi][0] = *(const float4*)&As[s][wm * 32 + mi * 16 + fr][fc * 4];
            av[mi][1] = *(const float4*)&As[s][wm * 32 + mi * 16 + fr + 8][fc * 4];
        }
        #pragma unroll
        for (int nh = 0; nh < 2; nh++) {
            float4 bv[4];
            #pragma unroll
            for (int nj = 0; nj < 4; nj++)
                bv[nj] = *(const float4*)&Bs[s][wn * 64 + (nh * 4 + nj) * 8 + fr][fc * 4];
            #pragma unroll
            for (int mi = 0; mi < 2; mi++)
                #pragma unroll
                for (int nj = 0; nj < 4; nj++) {
                    // group 0: logical ks (4fc, 4fc+1)
                    mma8(acc[mi][nh * 4 + nj],
                         make_float2(av[mi][0].x, av[mi][0].y),
                         make_float2(av[mi][1].x, av[mi][1].y),
                         make_float2(bv[nj].x, bv[nj].y));
                    // group 1: logical ks (4fc+2, 4fc+3)
                    mma8(acc[mi][nh * 4 + nj],
                         make_float2(av[mi][0].z, av[mi][0].w),
                         make_float2(av[mi][1].z, av[mi][1].w),
                         make_float2(bv[nj].z, bv[nj].w));
                }
        }
    };

    // ---- prologue: 2 stages in flight ----
    fetch(0, 0); CP_COMMIT();
    fetch(1, 1); CP_COMMIT();
    CP_WAIT1();
    __syncthreads();

    int cur = 0;
    for (int kt = 0; kt < nkt; kt++) {
        compute(cur);
        if (kt + 1 < nkt) {
            __syncthreads();                 // buf cur fully consumed
            if (kt + 2 < nkt) fetch(kt + 2, cur);
            CP_COMMIT();
            CP_WAIT1();                      // stage kt+1 landed
            __syncthreads();
            cur ^= 1;
        }
    }

    // Epilogue: c0,c1 -> row fr, cols 2fc,2fc+1; c2,c3 -> row fr+8.
    #pragma unroll
    for (int mi = 0; mi < 2; mi++) {
        #pragma unroll
        for (int h = 0; h < 2; h++) {
            int row = m0 + wm * 32 + mi * 16 + h * 8 + fr;
            float rsc = (MODE == 3) ? g_inv[row] : scale;
            #pragma unroll
            for (int ni = 0; ni < 8; ni++) {
                int col = n0 + wn * 64 + ni * 8 + 2 * fc;
                float v0 = acc[mi][ni][h * 2 + 0] * rsc;
                float v1 = acc[mi][ni][h * 2 + 1] * rsc;
                if (bias) { v0 += bias[col]; v1 += bias[col + 1]; }
                if (resid) {
                    float2 r = *(const float2*)(resid + (size_t)row * ldc + col);
                    v0 += r.x; v1 += r.y;
                }
                if (do_round) { v0 = tf32r(v0); v1 = tf32r(v1); }
                float2 o; o.x = v0; o.y = v1;
                *(float2*)(C + (size_t)row * ldc + col) = o;
            }
        }
    }
}

// ---------------------------------------------------------------------------
// Softmax over causal prefix L = (frame+1)*1024.  Unnormalized exp in g_S,
// 1/sum in g_inv (PV epilogue applies it).
// ---------------------------------------------------------------------------
__global__ void softmax_rows() {
    const int q = blockIdx.x;
    const int L = ((q >> 10) + 1) << 10;
    float* row = g_S + (size_t)q * S_TOT;
    __shared__ float red[256];
    const int tid = threadIdx.x;

    float m = -1e30f;
    for (int i = tid; i < L; i += 256) m = fmaxf(m, row[i]);
    red[tid] = m; __syncthreads();
    for (int o = 128; o > 0; o >>= 1) {
        if (tid < o) red[tid] = fmaxf(red[tid], red[tid + o]);
        __syncthreads();
    }
    m = red[0];
    __syncthreads();

    float s = 0.f;
    for (int i = tid; i < L; i += 256) {
        float e = tf32r(__expf(row[i] - m));
        row[i] = e;
        s += e;
    }
    red[tid] = s; __syncthreads();
    for (int o = 128; o > 0; o >>= 1) {
        if (tid < o) red[tid] += red[tid + o];
        __syncthreads();
    }
    if (tid == 0) g_inv[q] = 1.f / red[0];
}

// ---------------------------------------------------------------------------
// Host orchestration — kernel launches only (graph-capture safe).
// Launch order: first conv GEMM at index 3 (ncu capture slot).
// ---------------------------------------------------------------------------
extern "C" void kernel_launch(void* const* d_in, const int* in_sizes, int n_in,
                              void* d_out, int out_size) {
    (void)in_sizes; (void)n_in; (void)out_size;

    const float* in = (const float*)d_in[0];
    float* out = (float*)d_out;

    const dim3 gemm_grid(C_DIM / BN, S_TOT / BM);   // (4, 64)
    const int EW_BLOCKS = S_TOT * C_DIM / 256;
    const int WC_BLOCKS = 27 * C_DIM * C_DIM / 256;
    const int WL_BLOCKS = C_DIM * C_DIM / 256;
    const dim3 tb(32, 8);

    // ---- resnet block 0 ----
    {
        const float* n1s = (const float*)d_in[1];
        const float* n1b = (const float*)d_in[2];
        const float* w1  = (const float*)d_in[3];
        const float* b1  = (const float*)d_in[4];

        wconv_tr<<<WC_BLOCKS, 256>>>(w1);                                  // 0
        gn_stats_raw<<<NG, 1024>>>(in);                                    // 1
        gn_tr_apply<<<dim3(S_TOT / 32, C_DIM / 32), tb>>>(in, n1s, n1b);   // 2
        mma_gemm<1><<<gemm_grid, 256>>>(1, 8, b1, -1, 2,                   // 3 <- profiled
                                        27 * C_DIM, C_DIM, C_DIM, C_DIM, 1.f, 0);
        transpose_k<<<dim3(S_TOT / 32, C_DIM / 32), tb>>>(in, -1, nullptr, 0,
                                                          C_DIM, S_TOT);   // 4
        const float* n2s = (const float*)d_in[5];
        const float* n2b = (const float*)d_in[6];
        const float* w2  = (const float*)d_in[7];
        const float* b2  = (const float*)d_in[8];
        gn_stats<<<NG, 1024>>>(2);
        gn_apply<<<EW_BLOCKS, 256>>>(2, n2s, n2b, 1);
        wconv_tr<<<WC_BLOCKS, 256>>>(w2);
        mma_gemm<1><<<gemm_grid, 256>>>(1, 8, b2, 0, 0,
                                        27 * C_DIM, C_DIM, C_DIM, C_DIM, 1.f, 0);
    }

    auto resnet = [&](int base) {
        const float* n1s = (const float*)d_in[base + 0];
        const float* n1b = (const float*)d_in[base + 1];
        const float* w1  = (const float*)d_in[base + 2];
        const float* b1  = (const float*)d_in[base + 3];
        const float* n2s = (const float*)d_in[base + 4];
        const float* n2b = (const float*)d_in[base + 5];
        const float* w2  = (const float*)d_in[base + 6];
        const float* b2  = (const float*)d_in[base + 7];

        gn_stats<<<NG, 1024>>>(0);
        gn_apply<<<EW_BLOCKS, 256>>>(0, n1s, n1b, 1);
        wconv_tr<<<WC_BLOCKS, 256>>>(w1);
        mma_gemm<1><<<gemm_grid, 256>>>(1, 8, b1, -1, 2,
                                        27 * C_DIM, C_DIM, C_DIM, C_DIM, 1.f, 0);
        gn_stats<<<NG, 1024>>>(2);
        gn_apply<<<EW_BLOCKS, 256>>>(2, n2s, n2b, 1);
        wconv_tr<<<WC_BLOCKS, 256>>>(w2);
        mma_gemm<1><<<gemm_grid, 256>>>(1, 8, b2, 0, 0,
                                        27 * C_DIM, C_DIM, C_DIM, C_DIM, 1.f, 0);
    };

    // ---- causal frame attention (inputs 17..26) ----
    {
        const float* gns = (const float*)d_in[17];
        const float* gnb = (const float*)d_in[18];
        const float* wq  = (const float*)d_in[19];
        const float* bq  = (const float*)d_in[20];
        const float* wk  = (const float*)d_in[21];
        const float* bk  = (const float*)d_in[22];
        const float* wv  = (const float*)d_in[23];
        const float* bv  = (const float*)d_in[24];
        const float* wo  = (const float*)d_in[25];
        const float* bo  = (const float*)d_in[26];

        gn_stats<<<NG, 1024>>>(0);
        gn_apply<<<EW_BLOCKS, 256>>>(0, gns, gnb, 0);

        round_copy<<<WL_BLOCKS, 256>>>(wq);
        mma_gemm<0><<<gemm_grid, 256>>>(1, 9, bq, -1, 3,
                                        C_DIM, C_DIM, C_DIM, C_DIM, 1.f, 1);
        round_copy<<<WL_BLOCKS, 256>>>(wk);
        mma_gemm<0><<<gemm_grid, 256>>>(1, 9, bk, -1, 4,
                                        C_DIM, C_DIM, C_DIM, C_DIM, 1.f, 1);
        round_copy<<<WL_BLOCKS, 256>>>(wv);
        mma_gemm<0><<<gemm_grid, 256>>>(1, 9, bv, -1, 5,
                                        C_DIM, C_DIM, C_DIM, C_DIM, 1.f, 1);

        const float scale = 0.044194173824159216f;  // 512^-0.5
        mma_gemm<2><<<dim3(S_TOT / BN, S_TOT / BM), 256>>>(
            3, 4, nullptr, -1, 7, C_DIM, C_DIM, C_DIM, S_TOT, scale, 0);
        softmax_rows<<<S_TOT, 256>>>();

        transpose_k<<<dim3(C_DIM / 32, S_TOT / 32), tb>>>(nullptr, 5, nullptr, 2,
                                                          S_TOT, C_DIM);
        mma_gemm<3><<<gemm_grid, 256>>>(7, 2, nullptr, -1, 6,
                                        S_TOT, S_TOT, S_TOT, C_DIM, 1.f, 1);

        round_copy<<<WL_BLOCKS, 256>>>(wo);
        mma_gemm<0><<<gemm_grid, 256>>>(6, 9, bo, 0, 0,
                                        C_DIM, C_DIM, C_DIM, C_DIM, 1.f, 0);
    }

    // ---- resnet block 1 (inputs 9..16) ----
    resnet(9);

    // channels-last g_X[8192][512] -> NCDHW out [512][8192]
    transpose_k<<<dim3(C_DIM / 32, S_TOT / 32), tb>>>(nullptr, 0, out, -1, S_TOT, C_DIM);
}